// round 17
// baseline (speedup 1.0000x reference)
#include <cuda_runtime.h>
#include <cuda_fp16.h>
#include <cstdint>

#define Tt 512
#define Hh 512
#define Ff 256
#define Bb 256
#define NCTA 128
#define TPB  256

#define WSTR_E 776             // padded W row stride (elements); 1552 B
#define WSTR_B 1552
#define WHI_OFF 0
#define WLO_OFF (32 * WSTR_B)
#define A_OFF   (2 * 32 * WSTR_B)          // 99328
#define SA_STR  144                         // A row stride bytes (128B data + 16B pad)
#define CHUNKB  (32 * SA_STR)               // 4608
#define A_BYTES (16 * CHUNKB)               // 73728: 8 h + 4 x_hi + 4 x_lo
#define MB_OFF  (A_OFF + A_BYTES)           // 173056
#define SM_DYN  (MB_OFF + 64)               // 173120

__device__ __align__(1024) __half g_xfh[(size_t)Bb * Tt * Ff];   // x fp16 hi
__device__ __align__(1024) __half g_xfl[(size_t)Bb * Tt * Ff];   // x fp16 residual
__device__ __align__(1024) __half g_hf[2][Bb * Hh];              // h fp16 (single term)
__device__ unsigned g_pflag[8 * 16 * 16];  // [mq][nq] producer flags, 64B apart
__device__ unsigned g_exit;

// ---------------- helpers ----------------
__device__ __forceinline__ uint32_t smem_u32(const void* p) {
    uint32_t a;
    asm("{ .reg .u64 t; cvta.to.shared.u64 t, %1; cvt.u32.u64 %0, t; }" : "=r"(a) : "l"(p));
    return a;
}
__device__ __forceinline__ void cp_async16(uint32_t dst, const void* src) {
    asm volatile("cp.async.cg.shared.global [%0], [%1], 16;" :: "r"(dst), "l"(src) : "memory");
}
__device__ __forceinline__ void mbar_init(uint32_t a, uint32_t c) {
    asm volatile("mbarrier.init.shared.b64 [%0], %1;" :: "r"(a), "r"(c) : "memory");
}
__device__ __forceinline__ void cpa_arrive(uint32_t a) {
    asm volatile("cp.async.mbarrier.arrive.noinc.shared.b64 [%0];" :: "r"(a) : "memory");
}
__device__ __forceinline__ void mbar_wait(uint32_t a, uint32_t par) {
    uint32_t done;
    do {
        asm volatile("{\n\t.reg .pred p;\n\t"
                     "mbarrier.try_wait.parity.shared::cta.b64 p, [%1], %2, 0x989680;\n\t"
                     "selp.b32 %0, 1, 0, p;\n\t}"
                     : "=r"(done) : "r"(a), "r"(par) : "memory");
    } while (!done);
}
__device__ __forceinline__ void ldm_x4(uint32_t& r0, uint32_t& r1, uint32_t& r2, uint32_t& r3,
                                       uint32_t addr) {
    asm volatile("ldmatrix.sync.aligned.m8n8.x4.shared.b16 {%0,%1,%2,%3}, [%4];"
                 : "=r"(r0), "=r"(r1), "=r"(r2), "=r"(r3) : "r"(addr));
}
__device__ __forceinline__ void ldm_x2(uint32_t& r0, uint32_t& r1, uint32_t addr) {
    asm volatile("ldmatrix.sync.aligned.m8n8.x2.shared.b16 {%0,%1}, [%2];"
                 : "=r"(r0), "=r"(r1) : "r"(addr));
}
__device__ __forceinline__ void mma16816(float* d, const uint32_t* a, uint32_t b0, uint32_t b1) {
    asm volatile("mma.sync.aligned.m16n8k16.row.col.f32.f16.f16.f32 "
                 "{%0,%1,%2,%3}, {%4,%5,%6,%7}, {%8,%9}, {%0,%1,%2,%3};"
                 : "+f"(d[0]), "+f"(d[1]), "+f"(d[2]), "+f"(d[3])
                 : "r"(a[0]), "r"(a[1]), "r"(a[2]), "r"(a[3]), "r"(b0), "r"(b1));
}
__device__ __forceinline__ uint32_t packh(__half a, __half b) {
    return (uint32_t)__half_as_ushort(a) | ((uint32_t)__half_as_ushort(b) << 16);
}
__device__ __forceinline__ void stcg32(void* p, uint32_t v) {
    asm volatile("st.global.cg.b32 [%0], %1;" :: "l"(p), "r"(v) : "memory");
}
__device__ __forceinline__ float tanh_acc(float x) {
    float e = __expf(2.f * x);               // inf-safe
    return 1.f - __fdividef(2.f, e + 1.f);   // rcp.approx path
}

// ---------------- prep: split x into fp16 hi/lo ----------------
__global__ void xsplit(const float* __restrict__ x) {
    size_t base = ((size_t)blockIdx.x * 256 + threadIdx.x) * 8;
    float4 v0 = __ldg((const float4*)(x + base));
    float4 v1 = __ldg((const float4*)(x + base) + 1);
    float v[8] = {v0.x, v0.y, v0.z, v0.w, v1.x, v1.y, v1.z, v1.w};
    uint32_t ph[4], pl[4];
    #pragma unroll
    for (int j = 0; j < 4; j++) {
        __half h0 = __float2half_rn(v[2*j]);
        __half h1 = __float2half_rn(v[2*j+1]);
        __half l0 = __float2half_rn(v[2*j]   - __half2float(h0));
        __half l1 = __float2half_rn(v[2*j+1] - __half2float(h1));
        ph[j] = packh(h0, h1); pl[j] = packh(l0, l1);
    }
    *(uint4*)&g_xfh[base] = make_uint4(ph[0], ph[1], ph[2], ph[3]);
    *(uint4*)&g_xfl[base] = make_uint4(pl[0], pl[1], pl[2], pl[3]);
}

// chunk ids: 0-7 h (single fp16), 8-11 x_hi, 12-15 x_lo
// kg: W K-block index. both: also accumulate the W_lo term.
// Warp-complete-K: one n8 output per warp -> one mma per k16 per term.
__device__ __forceinline__ void compute_chunk(bool both, int c, int kg, uint32_t aBase,
                                              uint32_t bHi, uint32_t bLo,
                                              float* Da, float* Db) {
    const uint32_t kg2 = (uint32_t)kg * 128;
    const uint32_t ab = aBase + (uint32_t)c * CHUNKB;
    #pragma unroll
    for (int k16 = 0; k16 < 4; k16++) {
        float* P = (k16 & 1) ? Db : Da;
        uint32_t a[4], b0, b1;
        ldm_x4(a[0], a[1], a[2], a[3], ab + k16 * 32);
        ldm_x2(b0, b1, bHi + kg2 + k16 * 32);
        mma16816(P, a, b0, b1);
        if (both) {
            ldm_x2(b0, b1, bLo + kg2 + k16 * 32);
            mma16816(P, a, b0, b1);
        }
    }
}

// ---------------- persistent HMMA recurrence, warp-complete-K 16x8 tiles ----------------
__global__ void __launch_bounds__(TPB, 1)
rnn_mma(const float* __restrict__ Wx, const float* __restrict__ Wh,
        const float* __restrict__ bias, const float* __restrict__ Wfc,
        const float* __restrict__ bfc, float* __restrict__ out)
{
    extern __shared__ char sm[];
    const uint32_t s0 = smem_u32(sm);

    const int tid  = threadIdx.x;
    const int wid  = tid >> 5, lane = tid & 31;
    const int mq   = blockIdx.x >> 4;
    const int nq   = blockIdx.x & 15;
    const int mbase = mq * 32, qn = nq * 32;
    const int m_off = (wid & 1) * 16;       // warp tile: 16 rows x 8 cols
    const int n_off = (wid >> 1) * 8;

    unsigned* myflag = &g_pflag[(mq * 16 + nq) * 16];
    unsigned* grpflags = &g_pflag[mq * 16 * 16];

    const uint32_t MBQ = s0 + MB_OFF;
    const uint32_t MBX = s0 + MB_OFF + 32;

    if (tid == 0) {
        #pragma unroll
        for (int i = 0; i < 4; i++) mbar_init(MBQ + 8 * i, 32);   // one issuing warp per quad
        mbar_init(MBX, 256);
    }

    // resident [Wh;Wx] fp16 hi/lo split slice: [n<32][k<768]
    __half* sWhi = (__half*)(sm + WHI_OFF);
    __half* sWlo = (__half*)(sm + WLO_OFF);
    for (int idx = tid; idx < 32 * 768; idx += TPB) {
        int n = idx / 768, k = idx - n * 768;
        float w = (k < 512) ? Wh[k * Hh + qn + n] : Wx[(k - 512) * Hh + qn + n];
        __half hi = __float2half_rn(w);
        sWhi[n * WSTR_E + k] = hi;
        sWlo[n * WSTR_E + k] = __float2half_rn(w - __half2float(hi));
    }
    __syncthreads();   // mbar init + W visible

    // fragment addresses (invariant)
    const uint32_t aoff = (uint32_t)(m_off + (lane & 15)) * SA_STR + ((lane >> 4) << 4);
    // B n8 fragment: lanes 0-15 address rows n_off+(lane&7), 16B col seg (lane>>3)&1
    const uint32_t boff = (uint32_t)(n_off + (lane & 7)) * WSTR_B + (((lane >> 3) & 1) << 4);
    const uint32_t aBase = s0 + A_OFF + aoff;
    const uint32_t bHi   = s0 + WHI_OFF + boff;
    const uint32_t bLo   = s0 + WLO_OFF + boff;

    // x producers: all 256 threads
    const int irow = tid >> 3;
    const int iseg = tid & 7;
    const uint32_t pdst0 = s0 + A_OFF + (uint32_t)irow * SA_STR + (uint32_t)iseg * 16;

    // h quad-issue mapping (warps 0-3): lane -> 8 rows (lane>>3 + j*4), seg lane&7
    const int qrow = lane >> 3;
    const int qseg = lane & 7;

    // epilogue constants (warp-local 16x8 tile)
    const int ec = qn + n_off + (lane & 3) * 2;
    const int er = mbase + m_off + (lane >> 2);
    const float eb0 = bias[ec], eb1 = bias[ec + 1];

    #define ISSUE(s, c) do {                                                                  \
        int _c = (c);                                                                         \
        const __half* _src;                                                                   \
        if (_c < 12) _src = g_xfh + ((size_t)(mbase + irow) * Tt + (s)) * Ff + (_c - 8) * 64;  \
        else         _src = g_xfl + ((size_t)(mbase + irow) * Tt + (s)) * Ff + (_c - 12) * 64; \
        cp_async16(pdst0 + (uint32_t)_c * CHUNKB, (const char*)_src + iseg * 16);             \
    } while (0)

    #define ISSUE_X(s) do {                                                                   \
        ISSUE(s, 8); ISSUE(s, 9); ISSUE(s, 10); ISSUE(s, 11);                                 \
        ISSUE(s, 12); ISSUE(s, 13); ISSUE(s, 14); ISSUE(s, 15);                               \
        cpa_arrive(MBX);                                                                      \
    } while (0)

    // prefetch x(0)
    ISSUE_X(0);

    for (int t = 0; t < Tt; ++t) {
        float Da[4] = {0,0,0,0}, Db[4] = {0,0,0,0};

        if (t && wid < 4) {
            // ---- warp `wid` gates + issues quad `wid` (producers 4*wid..4*wid+3) ----
            if (lane < 4) {
                while (*(volatile unsigned*)&grpflags[(4 * wid + lane) * 16] < (unsigned)t) { }
            }
            __syncwarp();
            const __half* hf = g_hf[t & 1] + (size_t)mbase * Hh + (2 * wid) * 64;
            #pragma unroll
            for (int j = 0; j < 8; j++) {
                const int row = qrow + j * 4;
                const uint32_t dst = s0 + A_OFF + (uint32_t)row * SA_STR + (uint32_t)qseg * 16;
                const char* sh = (const char*)(hf + (size_t)row * Hh) + qseg * 16;
                cp_async16(dst + (uint32_t)(2 * wid)     * CHUNKB, sh);
                cp_async16(dst + (uint32_t)(2 * wid + 1) * CHUNKB, sh + 128);
            }
            cpa_arrive(MBQ + 8 * wid);
        }

        // x(t) compute: every warp covers full K (fills poll/issue bubble)
        mbar_wait(MBX, t & 1);
        #pragma unroll
        for (int c = 0; c < 4; c++)
            compute_chunk(true, 8 + c, 8 + c, aBase, bHi, bLo, Da, Db);   // x_hi (2-term)
        #pragma unroll
        for (int c = 0; c < 4; c++)
            compute_chunk(false, 12 + c, 8 + c, aBase, bHi, bLo, Da, Db); // x_lo @ W_hi
        __syncthreads();                       // all warps done reading x slots
        if (t + 1 < Tt) ISSUE_X(t + 1);

        if (t) {
            // drain h quads: full K per warp, single-term h @ W_hi
            #pragma unroll
            for (int q = 0; q < 4; q++) {
                mbar_wait(MBQ + 8 * q, (t - 1) & 1);
                compute_chunk(false, 2*q,     2*q,     aBase, bHi, bLo, Da, Db);
                compute_chunk(false, 2*q + 1, 2*q + 1, aBase, bHi, bLo, Da, Db);
            }
        }

        // ---- warp-local epilogue: accumulators are complete (no reduction) ----
        {
            float h0 = tanh_acc(Da[0] + Db[0] + eb0);
            float h1 = tanh_acc(Da[1] + Db[1] + eb1);
            float h2 = tanh_acc(Da[2] + Db[2] + eb0);
            float h3 = tanh_acc(Da[3] + Db[3] + eb1);

            const int nxt = (t & 1) ^ 1;
            __half* dh = g_hf[nxt];
            size_t o0 = (size_t)er * Hh + ec;
            size_t o1 = (size_t)(er + 8) * Hh + ec;
            stcg32(dh + o0, packh(__float2half_rn(h0), __float2half_rn(h1)));
            stcg32(dh + o1, packh(__float2half_rn(h2), __float2half_rn(h3)));
        }
        __syncthreads();

        // publish: fire-and-forget per-producer flag
        if (tid == 0) {
            __threadfence();
            atomicExch(myflag, (unsigned)(t + 1));
        }
    }
    #undef ISSUE_X
    #undef ISSUE

    // ---- final Dense(1): per-group, CTA nq==0 handles its 32 rows ----
    if (nq == 0) {
        if (tid < 16) {
            while (*(volatile unsigned*)&grpflags[tid * 16] < (unsigned)Tt) { }
        }
        __syncthreads();
        if (tid == 0) __threadfence();
        __syncthreads();
        const int brow = mbase + (tid >> 3);
        const int l = tid & 7;
        float s = 0.f;
        const __half* hf = g_hf[0] + (size_t)brow * Hh;
        for (int k = l; k < Hh; k += 8) {
            s += __half2float(__ldcg(&hf[k])) * __ldg(&Wfc[k]);
        }
        s += __shfl_down_sync(0xffffffffu, s, 4, 8);
        s += __shfl_down_sync(0xffffffffu, s, 2, 8);
        s += __shfl_down_sync(0xffffffffu, s, 1, 8);
        if (l == 0) out[brow] = s + __ldg(bfc) - 0.05f;
    }

    // ---- exit: last CTA resets flag state for graph replay ----
    __syncthreads();
    if (tid == 0) {
        __threadfence();
        unsigned e = atomicAdd(&g_exit, 1u);
        if (e == (unsigned)(NCTA - 1)) {
            for (int i = 0; i < 8 * 16; i++) g_pflag[i * 16] = 0u;
            g_exit = 0u;
            __threadfence();
        }
    }
}

extern "C" void kernel_launch(void* const* d_in, const int* in_sizes, int n_in,
                              void* d_out, int out_size) {
    const float* x   = (const float*)d_in[0];
    const float* Wx  = (const float*)d_in[1];
    const float* Wh  = (const float*)d_in[2];
    const float* b   = (const float*)d_in[3];
    const float* Wfc = (const float*)d_in[4];
    const float* bfc = (const float*)d_in[5];
    float* out = (float*)d_out;
    (void)in_sizes; (void)n_in; (void)out_size;

    cudaFuncSetAttribute(rnn_mma, cudaFuncAttributeMaxDynamicSharedMemorySize, SM_DYN);
    xsplit<<<16384, 256>>>(x);
    rnn_mma<<<NCTA, TPB, SM_DYN>>>(Wx, Wh, b, Wfc, bfc, out);
}